// round 4
// baseline (speedup 1.0000x reference)
#include <cuda_runtime.h>
#include <cuda_fp16.h>
#include <cstdint>

// ---------------------------------------------------------------------------
// Problem constants
// ---------------------------------------------------------------------------
#define BROWS 4096
#define DDIM  4096
#define OROWS 4096
#define MBUCK 2048

#define GM 4096
#define GN 4096
#define PK 4096            // panel K: [hi(0:2048) | lo(2048:4096)]
#define BM 128
#define BN 128
#define BK 64
#define NKT 96             // 3 phases x 32 k-tiles
// phase 0 (kt  0..31): Ahi x Bhi, f32 accum
// phase 1 (kt 32..63): Ahi x Blo, f16 accum
// phase 2 (kt 64..95): Alo x Bhi, f16 accum

#define A_TILE_B 16384
#define STAGE_B  32768
#define NSTAGE   3
#define SMEM_TOTAL (NSTAGE * STAGE_B)   // 98304

// ---------------------------------------------------------------------------
// Scratch panels (fp16, row-major [rows][4096])
// ---------------------------------------------------------------------------
__device__ __align__(16) __half g_A[(size_t)GM * PK];  // 32 MB
__device__ __align__(16) __half g_B[(size_t)GN * PK];  // 32 MB

// ---------------------------------------------------------------------------
// Sketch kernel: 4 rows per block; shared-atomic scatter-add; fp32 ->
// (fp16 hi, fp16 lo) split written into [hi|lo] panels.
// ---------------------------------------------------------------------------
__global__ __launch_bounds__(256) void sketch_kernel(
    const float* __restrict__ x,
    const int*   __restrict__ hidx,
    const float* __restrict__ sgn,
    int which)   // 0 -> A panel, 1 -> B panel
{
    __shared__ __align__(16) float acc[4][MBUCK];
    const int row0 = blockIdx.x * 4;
    const int tid = threadIdx.x;

    for (int i = tid; i < 4 * MBUCK; i += 256) ((float*)acc)[i] = 0.0f;
    __syncthreads();

    const int4*   h4 = (const int4*)hidx;
    const float4* s4 = (const float4*)sgn;

    #pragma unroll
    for (int it = 0; it < DDIM / 4 / 256; ++it) {   // 4 iters
        const int idx = it * 256 + tid;
        const int4   hv = h4[idx];
        const float4 sv = s4[idx];
        #pragma unroll
        for (int r = 0; r < 4; ++r) {
            const float4 xv = *(const float4*)(x + (size_t)(row0 + r) * DDIM + idx * 4);
            atomicAdd(&acc[r][hv.x], xv.x * sv.x);
            atomicAdd(&acc[r][hv.y], xv.y * sv.y);
            atomicAdd(&acc[r][hv.z], xv.z * sv.z);
            atomicAdd(&acc[r][hv.w], xv.w * sv.w);
        }
    }
    __syncthreads();

    const int k0 = tid * 8;
    __half* pan = which ? g_B : g_A;
    #pragma unroll
    for (int r = 0; r < 4; ++r) {
        uint32_t hw[4], lw[4];
        #pragma unroll
        for (int j = 0; j < 4; ++j) {
            float v0 = acc[r][k0 + 2 * j], v1 = acc[r][k0 + 2 * j + 1];
            __half h0 = __float2half_rn(v0);
            __half h1 = __float2half_rn(v1);
            __half l0 = __float2half_rn(v0 - __half2float(h0));
            __half l1 = __float2half_rn(v1 - __half2float(h1));
            __half2 hp = __halves2half2(h0, h1);
            __half2 lp = __halves2half2(l0, l1);
            hw[j] = *(uint32_t*)&hp;
            lw[j] = *(uint32_t*)&lp;
        }
        __half* base = pan + (size_t)(row0 + r) * PK + k0;
        *(uint4*)(base)        = make_uint4(hw[0], hw[1], hw[2], hw[3]);
        *(uint4*)(base + 2048) = make_uint4(lw[0], lw[1], lw[2], lw[3]);
    }
}

// ---------------------------------------------------------------------------
// GEMM helpers
// ---------------------------------------------------------------------------
__device__ __forceinline__ uint32_t sm_u32(const void* p) {
    uint32_t r;
    asm("{ .reg .u64 t; cvta.to.shared.u64 t, %1; cvt.u32.u64 %0, t; }"
        : "=r"(r) : "l"(p));
    return r;
}

#define CP_ASYNC16(saddr, gaddr) \
    asm volatile("cp.async.cg.shared.global [%0], [%1], 16;" \
                 :: "r"(saddr), "l"(gaddr))
#define CP_COMMIT() asm volatile("cp.async.commit_group;")
#define CP_WAIT(n)  asm volatile("cp.async.wait_group %0;" :: "n"(n))

#define LDMATRIX_X4(r0, r1, r2, r3, addr) \
    asm volatile("ldmatrix.sync.aligned.m8n8.x4.shared.b16 {%0,%1,%2,%3}, [%4];" \
                 : "=r"(r0), "=r"(r1), "=r"(r2), "=r"(r3) : "r"(addr))

#define MMA_16816_F32(d, a, b) \
    asm volatile("mma.sync.aligned.m16n8k16.row.col.f32.f16.f16.f32 " \
                 "{%0,%1,%2,%3}, {%4,%5,%6,%7}, {%8,%9}, {%0,%1,%2,%3};" \
                 : "+f"(d[0]), "+f"(d[1]), "+f"(d[2]), "+f"(d[3]) \
                 : "r"(a[0]), "r"(a[1]), "r"(a[2]), "r"(a[3]), \
                   "r"(b[0]), "r"(b[1]))

#define MMA_16816_F16(d, a, b) \
    asm volatile("mma.sync.aligned.m16n8k16.row.col.f16.f16.f16.f16 " \
                 "{%0,%1}, {%2,%3,%4,%5}, {%6,%7}, {%0,%1};" \
                 : "+r"(d[0]), "+r"(d[1]) \
                 : "r"(a[0]), "r"(a[1]), "r"(a[2]), "r"(a[3]), \
                   "r"(b[0]), "r"(b[1]))

// ---------------------------------------------------------------------------
// GEMM-NT: C = Ahi*Bhi^T (f32 acc) + Ahi*Blo^T + Alo*Bhi^T (f16 acc) + bias
// 8 warps (4M x 2N), warp tile 32x64, BK=64, 3-stage cp.async, 1 CTA/SM.
// ---------------------------------------------------------------------------
__global__ __launch_bounds__(256, 1) void gemm_kernel(
    const float* __restrict__ bias,
    float* __restrict__ C)
{
    extern __shared__ char smem[];
    const uint32_t sb = sm_u32(smem);
    const int tid  = threadIdx.x;
    const int wid  = tid >> 5;
    const int lane = tid & 31;
    const int wm = wid >> 1;           // 0..3
    const int wn = wid & 1;            // 0..1
    const int bm = blockIdx.y * BM;
    const int bn = blockIdx.x * BN;

    const __half* gA = g_A + (size_t)bm * PK;
    const __half* gB = g_B + (size_t)bn * PK;

    const int lr = tid >> 3;           // 0..31
    const int lc = tid & 7;            // chunk 0..7

    float    accf[2][8][4];
    uint32_t acch[2][8][2];
    #pragma unroll
    for (int mi = 0; mi < 2; ++mi)
        #pragma unroll
        for (int ni = 0; ni < 8; ++ni) {
            #pragma unroll
            for (int j = 0; j < 4; ++j) accf[mi][ni][j] = 0.0f;
            acch[mi][ni][0] = 0u; acch[mi][ni][1] = 0u;
        }

    uint32_t s_store[2][4];
    #pragma unroll
    for (int p = 0; p < 4; ++p) {
        int r = p * 32 + lr;
        uint32_t off = (uint32_t)r * 128 + (uint32_t)((lc ^ (r & 7)) << 4);
        s_store[0][p] = sb + off;
        s_store[1][p] = sb + A_TILE_B + off;
    }

    const int a_row0 = wm * 32 + (lane & 15);
    const int a_kcb  = lane >> 4;
    const int b_n0   = wn * 64 + ((lane >> 4) << 3) + (lane & 7);
    const int b_kcb  = (lane >> 3) & 1;

    #define LOAD_STAGE(slot, kt2)                                              \
        do {                                                                   \
            const int kA_ = ((kt2) < 32) ? (kt2) : (kt2) - 32;                 \
            const int kB_ = ((kt2) < 64) ? (kt2) : (kt2) - 64;                 \
            const __half* ga = gA + (size_t)kA_ * BK;                          \
            const __half* gb = gB + (size_t)kB_ * BK;                          \
            const uint32_t so = (uint32_t)(slot) * STAGE_B;                    \
            _Pragma("unroll")                                                  \
            for (int p = 0; p < 4; ++p) {                                      \
                int r = p * 32 + lr;                                           \
                CP_ASYNC16(s_store[0][p] + so,                                 \
                           (uint64_t)(ga + (size_t)r * PK + lc * 8));          \
                CP_ASYNC16(s_store[1][p] + so,                                 \
                           (uint64_t)(gb + (size_t)r * PK + lc * 8));          \
            }                                                                  \
            CP_COMMIT();                                                       \
        } while (0)

    LOAD_STAGE(0, 0);
    LOAD_STAGE(1, 1);

    for (int kt = 0; kt < NKT; ++kt) {
        const int slot = kt % NSTAGE;
        if (kt + 2 < NKT) {
            LOAD_STAGE((kt + 2) % NSTAGE, kt + 2);
            CP_WAIT(2);
        } else if (kt + 1 < NKT) {
            CP_WAIT(1);
        } else {
            CP_WAIT(0);
        }
        __syncthreads();

        const uint32_t sA = sb + (uint32_t)slot * STAGE_B;
        const uint32_t sB = sA + A_TILE_B;

        if (kt < 32) {
            #pragma unroll
            for (int k16 = 0; k16 < BK / 16; ++k16) {
                uint32_t a[2][4];
                #pragma unroll
                for (int mi = 0; mi < 2; ++mi) {
                    int row = a_row0 + mi * 16;
                    int kc = k16 * 2 + a_kcb;
                    uint32_t addr = sA + (uint32_t)row * 128
                                  + (uint32_t)((kc ^ (row & 7)) << 4);
                    LDMATRIX_X4(a[mi][0], a[mi][1], a[mi][2], a[mi][3], addr);
                }
                uint32_t b[8][2];
                #pragma unroll
                for (int nj = 0; nj < 4; ++nj) {
                    int n = b_n0 + nj * 16;
                    int kc = k16 * 2 + b_kcb;
                    uint32_t addr = sB + (uint32_t)n * 128
                                  + (uint32_t)((kc ^ (n & 7)) << 4);
                    LDMATRIX_X4(b[nj * 2][0], b[nj * 2][1],
                                b[nj * 2 + 1][0], b[nj * 2 + 1][1], addr);
                }
                #pragma unroll
                for (int mi = 0; mi < 2; ++mi)
                    #pragma unroll
                    for (int ni = 0; ni < 8; ++ni)
                        MMA_16816_F32(accf[mi][ni], a[mi], b[ni]);
            }
        } else {
            #pragma unroll
            for (int k16 = 0; k16 < BK / 16; ++k16) {
                uint32_t a[2][4];
                #pragma unroll
                for (int mi = 0; mi < 2; ++mi) {
                    int row = a_row0 + mi * 16;
                    int kc = k16 * 2 + a_kcb;
                    uint32_t addr = sA + (uint32_t)row * 128
                                  + (uint32_t)((kc ^ (row & 7)) << 4);
                    LDMATRIX_X4(a[mi][0], a[mi][1], a[mi][2], a[mi][3], addr);
                }
                uint32_t b[8][2];
                #pragma unroll
                for (int nj = 0; nj < 4; ++nj) {
                    int n = b_n0 + nj * 16;
                    int kc = k16 * 2 + b_kcb;
                    uint32_t addr = sB + (uint32_t)n * 128
                                  + (uint32_t)((kc ^ (n & 7)) << 4);
                    LDMATRIX_X4(b[nj * 2][0], b[nj * 2][1],
                                b[nj * 2 + 1][0], b[nj * 2 + 1][1], addr);
                }
                #pragma unroll
                for (int mi = 0; mi < 2; ++mi)
                    #pragma unroll
                    for (int ni = 0; ni < 8; ++ni)
                        MMA_16816_F16(acch[mi][ni], a[mi], b[ni]);
            }
        }
        __syncthreads();
    }

    // epilogue: f32 main + f16 corrections + bias
    #pragma unroll
    for (int mi = 0; mi < 2; ++mi) {
        const int r0 = bm + wm * 32 + mi * 16 + (lane >> 2);
        #pragma unroll
        for (int ni = 0; ni < 8; ++ni) {
            const int col = bn + wn * 64 + ni * 8 + (lane & 3) * 2;
            const float b0 = __ldg(bias + col);
            const float b1 = __ldg(bias + col + 1);
            const __half2 h01 = *(__half2*)&acch[mi][ni][0];
            const __half2 h23 = *(__half2*)&acch[mi][ni][1];
            float2 v0, v1;
            v0.x = accf[mi][ni][0] + __low2float(h01)  + b0;
            v0.y = accf[mi][ni][1] + __high2float(h01) + b1;
            v1.x = accf[mi][ni][2] + __low2float(h23)  + b0;
            v1.y = accf[mi][ni][3] + __high2float(h23) + b1;
            *(float2*)(C + (size_t)r0 * GN + col)       = v0;
            *(float2*)(C + (size_t)(r0 + 8) * GN + col) = v1;
        }
    }
}

// ---------------------------------------------------------------------------
// Launch
// ---------------------------------------------------------------------------
extern "C" void kernel_launch(void* const* d_in, const int* in_sizes, int n_in,
                              void* d_out, int out_size)
{
    const float* input  = (const float*)d_in[0];
    const float* weight = (const float*)d_in[1];
    const float* bias   = (const float*)d_in[2];
    const int*   hidx   = (const int*)d_in[3];
    const float* sgn    = (const float*)d_in[4];
    float* out = (float*)d_out;

    sketch_kernel<<<BROWS / 4, 256>>>(input,  hidx, sgn, 0);
    sketch_kernel<<<OROWS / 4, 256>>>(weight, hidx, sgn, 1);

    cudaFuncSetAttribute(gemm_kernel,
                         cudaFuncAttributeMaxDynamicSharedMemorySize, SMEM_TOTAL);
    dim3 grid(GN / BN, GM / BM);  // 32 x 32
    gemm_kernel<<<grid, 256, SMEM_TOTAL>>>(bias, out);
}

// round 5
// speedup vs baseline: 1.9209x; 1.9209x over previous
#include <cuda_runtime.h>
#include <cuda_fp16.h>
#include <cstdint>

// ---------------------------------------------------------------------------
// Problem constants
// ---------------------------------------------------------------------------
#define BROWS 4096
#define DDIM  4096
#define OROWS 4096
#define MBUCK 2048

#define GM 4096
#define GN 4096
#define GK 2048            // logical K (buckets)
#define PKA 4096           // A panel: [hi(0:2048) | lo(2048:4096)]
#define PKB 2048           // B panel: hi only
#define BM 128
#define BN 128
#define BK 64
#define NKT (GK / BK)      // 32 mainloop iterations (each does hi & lo A)

// smem stage = Ahi tile (16K) + Alo tile (16K) + B tile (16K)
#define T_B      16384
#define STAGE_B  49152
#define SMEM_TOTAL (2 * STAGE_B)   // 98304; 2 CTAs/SM -> 192KB/SM

// ---------------------------------------------------------------------------
// Scratch panels
// ---------------------------------------------------------------------------
__device__ __align__(16) __half g_A[(size_t)GM * PKA];  // 32 MB
__device__ __align__(16) __half g_B[(size_t)GN * PKB];  // 16 MB

// ---------------------------------------------------------------------------
// Sketch kernel: one block per row; shared-atomic scatter-add; fp32 ->
// fp16 split. A gets hi+lo, B gets hi only.
// ---------------------------------------------------------------------------
__global__ __launch_bounds__(256) void sketch_kernel(
    const float* __restrict__ x,
    const int*   __restrict__ hidx,
    const float* __restrict__ sgn,
    int which)   // 0 -> A panel (hi|lo), 1 -> B panel (hi)
{
    __shared__ __align__(16) float acc[MBUCK];
    const int row = blockIdx.x;
    const float4* xr = (const float4*)(x + (size_t)row * DDIM);
    const int4*   h4 = (const int4*)hidx;
    const float4* s4 = (const float4*)sgn;

    for (int i = threadIdx.x; i < MBUCK; i += 256) acc[i] = 0.0f;
    __syncthreads();

    #pragma unroll
    for (int it = 0; it < DDIM / 4 / 256; ++it) {
        int idx = it * 256 + threadIdx.x;
        float4 xv = xr[idx];
        int4   hv = h4[idx];
        float4 sv = s4[idx];
        atomicAdd(&acc[hv.x], xv.x * sv.x);
        atomicAdd(&acc[hv.y], xv.y * sv.y);
        atomicAdd(&acc[hv.z], xv.z * sv.z);
        atomicAdd(&acc[hv.w], xv.w * sv.w);
    }
    __syncthreads();

    const int k0 = threadIdx.x * 8;
    uint32_t hw[4], lw[4];
    #pragma unroll
    for (int j = 0; j < 4; ++j) {
        float v0 = acc[k0 + 2 * j], v1 = acc[k0 + 2 * j + 1];
        __half h0 = __float2half_rn(v0);
        __half h1 = __float2half_rn(v1);
        __half l0 = __float2half_rn(v0 - __half2float(h0));
        __half l1 = __float2half_rn(v1 - __half2float(h1));
        __half2 hp = __halves2half2(h0, h1);
        __half2 lp = __halves2half2(l0, l1);
        hw[j] = *(uint32_t*)&hp;
        lw[j] = *(uint32_t*)&lp;
    }
    uint4 hv4 = make_uint4(hw[0], hw[1], hw[2], hw[3]);
    uint4 lv4 = make_uint4(lw[0], lw[1], lw[2], lw[3]);

    if (which == 0) {
        __half* base = g_A + (size_t)row * PKA + k0;
        *(uint4*)(base)        = hv4;
        *(uint4*)(base + 2048) = lv4;
    } else {
        __half* base = g_B + (size_t)row * PKB + k0;
        *(uint4*)(base) = hv4;
    }
}

// ---------------------------------------------------------------------------
// GEMM helpers
// ---------------------------------------------------------------------------
__device__ __forceinline__ uint32_t sm_u32(const void* p) {
    uint32_t r;
    asm("{ .reg .u64 t; cvta.to.shared.u64 t, %1; cvt.u32.u64 %0, t; }"
        : "=r"(r) : "l"(p));
    return r;
}

#define CP_ASYNC16(saddr, gaddr) \
    asm volatile("cp.async.cg.shared.global [%0], [%1], 16;" \
                 :: "r"(saddr), "l"(gaddr))
#define CP_COMMIT() asm volatile("cp.async.commit_group;")
#define CP_WAIT(n)  asm volatile("cp.async.wait_group %0;" :: "n"(n))

#define LDMATRIX_X4(r0, r1, r2, r3, addr) \
    asm volatile("ldmatrix.sync.aligned.m8n8.x4.shared.b16 {%0,%1,%2,%3}, [%4];" \
                 : "=r"(r0), "=r"(r1), "=r"(r2), "=r"(r3) : "r"(addr))

#define MMA_16816(d, a, b) \
    asm volatile("mma.sync.aligned.m16n8k16.row.col.f32.f16.f16.f32 " \
                 "{%0,%1,%2,%3}, {%4,%5,%6,%7}, {%8,%9}, {%0,%1,%2,%3};" \
                 : "+f"(d[0]), "+f"(d[1]), "+f"(d[2]), "+f"(d[3]) \
                 : "r"(a[0]), "r"(a[1]), "r"(a[2]), "r"(a[3]), \
                   "r"(b[0]), "r"(b[1]))

// ---------------------------------------------------------------------------
// GEMM-NT: C = (Ahi + Alo) * Bhi^T + bias   (all f32 accumulation)
// Each mainloop iter: one B tile, MMA'd against both Ahi and Alo tiles.
// 8 warps (4M x 2N), warp tile 32x64, 2-stage cp.async, 2 CTAs/SM.
// ---------------------------------------------------------------------------
__global__ __launch_bounds__(256, 2) void gemm_kernel(
    const float* __restrict__ bias,
    float* __restrict__ C)
{
    extern __shared__ char smem[];
    const uint32_t sb = sm_u32(smem);
    const int tid  = threadIdx.x;
    const int wid  = tid >> 5;
    const int lane = tid & 31;
    const int wm = wid >> 1;           // 0..3
    const int wn = wid & 1;            // 0..1
    const int bm = blockIdx.y * BM;
    const int bn = blockIdx.x * BN;

    const __half* gA = g_A + (size_t)bm * PKA;
    const __half* gB = g_B + (size_t)bn * PKB;

    const int lr = tid >> 3;           // 0..31
    const int lc = tid & 7;            // chunk 0..7

    float acc[2][8][4];
    #pragma unroll
    for (int mi = 0; mi < 2; ++mi)
        #pragma unroll
        for (int ni = 0; ni < 8; ++ni)
            #pragma unroll
            for (int j = 0; j < 4; ++j) acc[mi][ni][j] = 0.0f;

    // swizzled smem store addresses for the 4 row-passes x 3 tiles
    uint32_t s_store[3][4];
    #pragma unroll
    for (int p = 0; p < 4; ++p) {
        int r = p * 32 + lr;
        uint32_t off = (uint32_t)r * 128 + (uint32_t)((lc ^ (r & 7)) << 4);
        s_store[0][p] = sb + off;              // Ahi
        s_store[1][p] = sb + T_B + off;        // Alo
        s_store[2][p] = sb + 2 * T_B + off;    // B
    }

    const int a_row0 = wm * 32 + (lane & 15);
    const int a_kcb  = lane >> 4;
    const int b_n0   = wn * 64 + ((lane >> 4) << 3) + (lane & 7);
    const int b_kcb  = (lane >> 3) & 1;

    #define LOAD_STAGE(slot, k)                                                \
        do {                                                                   \
            const __half* gah = gA + (size_t)(k) * BK;                         \
            const __half* gal = gA + 2048 + (size_t)(k) * BK;                  \
            const __half* gb_ = gB + (size_t)(k) * BK;                         \
            const uint32_t so = (uint32_t)(slot) * STAGE_B;                    \
            _Pragma("unroll")                                                  \
            for (int p = 0; p < 4; ++p) {                                      \
                int r = p * 32 + lr;                                           \
                CP_ASYNC16(s_store[0][p] + so,                                 \
                           (uint64_t)(gah + (size_t)r * PKA + lc * 8));        \
                CP_ASYNC16(s_store[1][p] + so,                                 \
                           (uint64_t)(gal + (size_t)r * PKA + lc * 8));        \
                CP_ASYNC16(s_store[2][p] + so,                                 \
                           (uint64_t)(gb_ + (size_t)r * PKB + lc * 8));        \
            }                                                                  \
            CP_COMMIT();                                                       \
        } while (0)

    LOAD_STAGE(0, 0);

    for (int kt = 0; kt < NKT; ++kt) {
        const int s = kt & 1;
        if (kt + 1 < NKT) {
            LOAD_STAGE(s ^ 1, kt + 1);
            CP_WAIT(1);
        } else {
            CP_WAIT(0);
        }
        __syncthreads();

        const uint32_t sAh = sb + (uint32_t)s * STAGE_B;
        const uint32_t sAl = sAh + T_B;
        const uint32_t sB  = sAh + 2 * T_B;

        #pragma unroll
        for (int k16 = 0; k16 < BK / 16; ++k16) {
            const int kc_a = k16 * 2 + a_kcb;
            const int kc_b = k16 * 2 + b_kcb;

            uint32_t ah[2][4], al[2][4];
            #pragma unroll
            for (int mi = 0; mi < 2; ++mi) {
                int row = a_row0 + mi * 16;
                uint32_t roff = (uint32_t)row * 128
                              + (uint32_t)((kc_a ^ (row & 7)) << 4);
                LDMATRIX_X4(ah[mi][0], ah[mi][1], ah[mi][2], ah[mi][3], sAh + roff);
                LDMATRIX_X4(al[mi][0], al[mi][1], al[mi][2], al[mi][3], sAl + roff);
            }
            uint32_t b[8][2];
            #pragma unroll
            for (int nj = 0; nj < 4; ++nj) {
                int n = b_n0 + nj * 16;
                uint32_t addr = sB + (uint32_t)n * 128
                              + (uint32_t)((kc_b ^ (n & 7)) << 4);
                LDMATRIX_X4(b[nj * 2][0], b[nj * 2][1],
                            b[nj * 2 + 1][0], b[nj * 2 + 1][1], addr);
            }
            #pragma unroll
            for (int mi = 0; mi < 2; ++mi)
                #pragma unroll
                for (int ni = 0; ni < 8; ++ni)
                    MMA_16816(acc[mi][ni], ah[mi], b[ni]);
            #pragma unroll
            for (int mi = 0; mi < 2; ++mi)
                #pragma unroll
                for (int ni = 0; ni < 8; ++ni)
                    MMA_16816(acc[mi][ni], al[mi], b[ni]);
        }
        __syncthreads();
    }

    // epilogue: add bias, store fp32
    #pragma unroll
    for (int mi = 0; mi < 2; ++mi) {
        const int r0 = bm + wm * 32 + mi * 16 + (lane >> 2);
        #pragma unroll
        for (int ni = 0; ni < 8; ++ni) {
            const int col = bn + wn * 64 + ni * 8 + (lane & 3) * 2;
            const float b0 = __ldg(bias + col);
            const float b1 = __ldg(bias + col + 1);
            float2 v0 = make_float2(acc[mi][ni][0] + b0, acc[mi][ni][1] + b1);
            float2 v1 = make_float2(acc[mi][ni][2] + b0, acc[mi][ni][3] + b1);
            *(float2*)(C + (size_t)r0 * GN + col)       = v0;
            *(float2*)(C + (size_t)(r0 + 8) * GN + col) = v1;
        }
    }
}

// ---------------------------------------------------------------------------
// Launch
// ---------------------------------------------------------------------------
extern "C" void kernel_launch(void* const* d_in, const int* in_sizes, int n_in,
                              void* d_out, int out_size)
{
    const float* input  = (const float*)d_in[0];
    const float* weight = (const float*)d_in[1];
    const float* bias   = (const float*)d_in[2];
    const int*   hidx   = (const int*)d_in[3];
    const float* sgn    = (const float*)d_in[4];
    float* out = (float*)d_out;

    sketch_kernel<<<BROWS, 256>>>(input,  hidx, sgn, 0);
    sketch_kernel<<<OROWS, 256>>>(weight, hidx, sgn, 1);

    cudaFuncSetAttribute(gemm_kernel,
                         cudaFuncAttributeMaxDynamicSharedMemorySize, SMEM_TOTAL);
    dim3 grid(GN / BN, GM / BM);  // 32 x 32
    gemm_kernel<<<grid, 256, SMEM_TOTAL>>>(bias, out);
}

// round 6
// speedup vs baseline: 2.9618x; 1.5419x over previous
#include <cuda_runtime.h>
#include <cuda_fp16.h>
#include <cstdint>

// ---------------------------------------------------------------------------
// Problem constants
// ---------------------------------------------------------------------------
#define BROWS 4096
#define DDIM  4096
#define OROWS 4096
#define MBUCK 2048

#define GM 4096
#define GN 4096
#define GK 2048            // K (buckets), pure fp16 single-term
#define BM 128
#define BN 128
#define BK 64
#define NKT (GK / BK)      // 32

// smem: 2 stages x (A 16KB + B 16KB)
#define A_TILE_B 16384
#define STAGE_B  32768
#define SMEM_TOTAL (2 * STAGE_B)   // 64KB; 2 CTAs/SM -> 128KB/SM

// ---------------------------------------------------------------------------
// Scratch panels (fp16 hi only, row-major [rows][2048])
// ---------------------------------------------------------------------------
__device__ __align__(16) __half g_A[(size_t)GM * GK];  // 16 MB
__device__ __align__(16) __half g_B[(size_t)GN * GK];  // 16 MB

// ---------------------------------------------------------------------------
// Sketch kernel: one block per row; shared-atomic scatter-add; fp32 -> fp16.
// ---------------------------------------------------------------------------
__global__ __launch_bounds__(256) void sketch_kernel(
    const float* __restrict__ x,
    const int*   __restrict__ hidx,
    const float* __restrict__ sgn,
    int which)   // 0 -> A panel, 1 -> B panel
{
    __shared__ __align__(16) float acc[MBUCK];
    const int row = blockIdx.x;
    const float4* xr = (const float4*)(x + (size_t)row * DDIM);
    const int4*   h4 = (const int4*)hidx;
    const float4* s4 = (const float4*)sgn;

    for (int i = threadIdx.x; i < MBUCK; i += 256) acc[i] = 0.0f;
    __syncthreads();

    #pragma unroll
    for (int it = 0; it < DDIM / 4 / 256; ++it) {
        int idx = it * 256 + threadIdx.x;
        float4 xv = xr[idx];
        int4   hv = h4[idx];
        float4 sv = s4[idx];
        atomicAdd(&acc[hv.x], xv.x * sv.x);
        atomicAdd(&acc[hv.y], xv.y * sv.y);
        atomicAdd(&acc[hv.z], xv.z * sv.z);
        atomicAdd(&acc[hv.w], xv.w * sv.w);
    }
    __syncthreads();

    const int k0 = threadIdx.x * 8;
    uint32_t hw[4];
    #pragma unroll
    for (int j = 0; j < 4; ++j) {
        __half2 hp = __halves2half2(__float2half_rn(acc[k0 + 2 * j]),
                                    __float2half_rn(acc[k0 + 2 * j + 1]));
        hw[j] = *(uint32_t*)&hp;
    }
    __half* base = (which ? g_B : g_A) + (size_t)row * GK + k0;
    *(uint4*)(base) = make_uint4(hw[0], hw[1], hw[2], hw[3]);
}

// ---------------------------------------------------------------------------
// GEMM helpers
// ---------------------------------------------------------------------------
__device__ __forceinline__ uint32_t sm_u32(const void* p) {
    uint32_t r;
    asm("{ .reg .u64 t; cvta.to.shared.u64 t, %1; cvt.u32.u64 %0, t; }"
        : "=r"(r) : "l"(p));
    return r;
}

#define CP_ASYNC16(saddr, gaddr) \
    asm volatile("cp.async.cg.shared.global [%0], [%1], 16;" \
                 :: "r"(saddr), "l"(gaddr))
#define CP_COMMIT() asm volatile("cp.async.commit_group;")
#define CP_WAIT(n)  asm volatile("cp.async.wait_group %0;" :: "n"(n))

#define LDMATRIX_X4(r0, r1, r2, r3, addr) \
    asm volatile("ldmatrix.sync.aligned.m8n8.x4.shared.b16 {%0,%1,%2,%3}, [%4];" \
                 : "=r"(r0), "=r"(r1), "=r"(r2), "=r"(r3) : "r"(addr))

#define MMA_16816(d, a, b) \
    asm volatile("mma.sync.aligned.m16n8k16.row.col.f32.f16.f16.f32 " \
                 "{%0,%1,%2,%3}, {%4,%5,%6,%7}, {%8,%9}, {%0,%1,%2,%3};" \
                 : "+f"(d[0]), "+f"(d[1]), "+f"(d[2]), "+f"(d[3]) \
                 : "r"(a[0]), "r"(a[1]), "r"(a[2]), "r"(a[3]), \
                   "r"(b[0]), "r"(b[1]))

// ---------------------------------------------------------------------------
// GEMM-NT: C[4096,4096] = A[4096,2048] * B[4096,2048]^T + bias   (fp16 in, f32 acc)
// 8 warps (4M x 2N), warp tile 32x64, BK=64, 2-stage cp.async, 2 CTAs/SM.
// ---------------------------------------------------------------------------
__global__ __launch_bounds__(256, 2) void gemm_kernel(
    const float* __restrict__ bias,
    float* __restrict__ C)
{
    extern __shared__ char smem[];
    const uint32_t sb = sm_u32(smem);
    const int tid  = threadIdx.x;
    const int wid  = tid >> 5;
    const int lane = tid & 31;
    const int wm = wid >> 1;           // 0..3
    const int wn = wid & 1;            // 0..1
    const int bm = blockIdx.y * BM;
    const int bn = blockIdx.x * BN;

    const __half* gA = g_A + (size_t)bm * GK;
    const __half* gB = g_B + (size_t)bn * GK;

    const int lr = tid >> 3;           // 0..31
    const int lc = tid & 7;            // chunk 0..7

    float acc[2][8][4];
    #pragma unroll
    for (int mi = 0; mi < 2; ++mi)
        #pragma unroll
        for (int ni = 0; ni < 8; ++ni)
            #pragma unroll
            for (int j = 0; j < 4; ++j) acc[mi][ni][j] = 0.0f;

    uint32_t s_store[2][4];
    #pragma unroll
    for (int p = 0; p < 4; ++p) {
        int r = p * 32 + lr;
        uint32_t off = (uint32_t)r * 128 + (uint32_t)((lc ^ (r & 7)) << 4);
        s_store[0][p] = sb + off;
        s_store[1][p] = sb + A_TILE_B + off;
    }

    const int a_row0 = wm * 32 + (lane & 15);
    const int a_kcb  = lane >> 4;
    const int b_n0   = wn * 64 + ((lane >> 4) << 3) + (lane & 7);
    const int b_kcb  = (lane >> 3) & 1;

    #define LOAD_STAGE(slot, k)                                                \
        do {                                                                   \
            const __half* ga = gA + (size_t)(k) * BK;                          \
            const __half* gb = gB + (size_t)(k) * BK;                          \
            const uint32_t so = (uint32_t)(slot) * STAGE_B;                    \
            _Pragma("unroll")                                                  \
            for (int p = 0; p < 4; ++p) {                                      \
                int r = p * 32 + lr;                                           \
                CP_ASYNC16(s_store[0][p] + so,                                 \
                           (uint64_t)(ga + (size_t)r * GK + lc * 8));          \
                CP_ASYNC16(s_store[1][p] + so,                                 \
                           (uint64_t)(gb + (size_t)r * GK + lc * 8));          \
            }                                                                  \
            CP_COMMIT();                                                       \
        } while (0)

    LOAD_STAGE(0, 0);

    for (int kt = 0; kt < NKT; ++kt) {
        const int s = kt & 1;
        if (kt + 1 < NKT) {
            LOAD_STAGE(s ^ 1, kt + 1);
            CP_WAIT(1);
        } else {
            CP_WAIT(0);
        }
        __syncthreads();

        const uint32_t sA = sb + (uint32_t)s * STAGE_B;
        const uint32_t sB = sA + A_TILE_B;

        #pragma unroll
        for (int k16 = 0; k16 < BK / 16; ++k16) {
            const int kc_a = k16 * 2 + a_kcb;
            const int kc_b = k16 * 2 + b_kcb;

            uint32_t a[2][4];
            #pragma unroll
            for (int mi = 0; mi < 2; ++mi) {
                int row = a_row0 + mi * 16;
                uint32_t addr = sA + (uint32_t)row * 128
                              + (uint32_t)((kc_a ^ (row & 7)) << 4);
                LDMATRIX_X4(a[mi][0], a[mi][1], a[mi][2], a[mi][3], addr);
            }
            uint32_t b[8][2];
            #pragma unroll
            for (int nj = 0; nj < 4; ++nj) {
                int n = b_n0 + nj * 16;
                uint32_t addr = sB + (uint32_t)n * 128
                              + (uint32_t)((kc_b ^ (n & 7)) << 4);
                LDMATRIX_X4(b[nj * 2][0], b[nj * 2][1],
                            b[nj * 2 + 1][0], b[nj * 2 + 1][1], addr);
            }
            #pragma unroll
            for (int mi = 0; mi < 2; ++mi)
                #pragma unroll
                for (int ni = 0; ni < 8; ++ni)
                    MMA_16816(acc[mi][ni], a[mi], b[ni]);
        }
        __syncthreads();
    }

    // epilogue: add bias, store fp32
    #pragma unroll
    for (int mi = 0; mi < 2; ++mi) {
        const int r0 = bm + wm * 32 + mi * 16 + (lane >> 2);
        #pragma unroll
        for (int ni = 0; ni < 8; ++ni) {
            const int col = bn + wn * 64 + ni * 8 + (lane & 3) * 2;
            const float b0 = __ldg(bias + col);
            const float b1 = __ldg(bias + col + 1);
            float2 v0 = make_float2(acc[mi][ni][0] + b0, acc[mi][ni][1] + b1);
            float2 v1 = make_float2(acc[mi][ni][2] + b0, acc[mi][ni][3] + b1);
            *(float2*)(C + (size_t)r0 * GN + col)       = v0;
            *(float2*)(C + (size_t)(r0 + 8) * GN + col) = v1;
        }
    }
}

// ---------------------------------------------------------------------------
// Launch
// ---------------------------------------------------------------------------
extern "C" void kernel_launch(void* const* d_in, const int* in_sizes, int n_in,
                              void* d_out, int out_size)
{
    const float* input  = (const float*)d_in[0];
    const float* weight = (const float*)d_in[1];
    const float* bias   = (const float*)d_in[2];
    const int*   hidx   = (const int*)d_in[3];
    const float* sgn    = (const float*)d_in[4];
    float* out = (float*)d_out;

    sketch_kernel<<<BROWS, 256>>>(input,  hidx, sgn, 0);
    sketch_kernel<<<OROWS, 256>>>(weight, hidx, sgn, 1);

    cudaFuncSetAttribute(gemm_kernel,
                         cudaFuncAttributeMaxDynamicSharedMemorySize, SMEM_TOTAL);
    dim3 grid(GN / BN, GM / BM);  // 32 x 32
    gemm_kernel<<<grid, 256, SMEM_TOTAL>>>(bias, out);
}